// round 3
// baseline (speedup 1.0000x reference)
#include <cuda_runtime.h>
#include <math.h>

// Problem constants
#define H_    112
#define W_    200
#define HW_   (H_*W_)        // 22400
#define C_    64
#define BN_   6
#define PAD_  4
#define HP_   (H_ + 2*PAD_)  // 120
#define WP_   (W_ + 2*PAD_)  // 208
#define HPWP_ (HP_*WP_)      // 24960
#define NTAP  81

typedef unsigned long long u64;

// ---- packed fp32x2 helpers (Blackwell) -------------------------------------
#define FFMA2(acc, a, b) asm("fma.rn.f32x2 %0, %1, %2, %3;" : "=l"(acc) : "l"(a), "l"(b), "l"(acc))
#define PACK2(d, lo, hi) asm("mov.b64 %0, {%1, %2};" : "=l"(d) : "f"(lo), "f"(hi))
#define UNPACK2(lo, hi, d) asm("mov.b64 {%0, %1}, %2;" : "=f"(lo), "=f"(hi) : "l"(d))
#define LDS64(d, addr) asm volatile("ld.shared.b64 %0, [%1];" : "=l"(d) : "r"(addr))

// ---------------- scratch (static device memory; no allocations) ------------
__device__ float4 g_q   [BN_*HW_*16];     // query,  [n][h][w][c] channel-last
__device__ float4 g_kpad[BN_*HPWP_*16];   // key,    [n][hp][wp][c] padded channel-last
__device__ float4 g_vpad[BN_*HPWP_*16];   // value,  padded channel-last
__device__ float  g_tmp [BN_*C_*HW_];     // intermediate conv activation (NCHW)
__device__ float  g_Wt  [5*64*64];        // folded weights, [layer][c_in][c_out]
__device__ float  g_bf  [5*64];           // folded bias

// ---------------- BN folding ------------------------------------------------
__global__ void prep_kernel(const float* __restrict__ wc, const float* __restrict__ g,
                            const float* __restrict__ b,  const float* __restrict__ m,
                            const float* __restrict__ v) {
    int idx = blockIdx.x * 256 + threadIdx.x;
    if (idx < 5*64*64) {
        int l  = idx >> 12;
        int r  = idx & 4095;
        int ci = r >> 6;
        int o  = r & 63;
        float s = g[l*64 + o] * rsqrtf(v[l*64 + o] + 1e-5f);
        g_Wt[idx] = s * wc[(l*64 + o)*64 + ci];   // transposed: [ci][o]
    }
    if (idx < 5*64) {
        float s = g[idx] * rsqrtf(v[idx] + 1e-5f);
        g_bf[idx] = b[idx] - s * m[idx];
    }
}

// ---------------- zero only the pad border of K/V ---------------------------
// border pixels per image: rows {0..3,116..119} all cols (1664) +
//                          rows 4..115, cols {0..3,204..207}   (896) = 2560
__global__ void zero_border_kernel() {
    int idx = blockIdx.x * 256 + threadIdx.x;       // [0, 6*2560)
    if (idx >= BN_ * 2560) return;
    int n = idx / 2560;
    int j = idx - n * 2560;
    int row, col;
    if (j < 1664) {
        int r = j / 208;
        col = j - r * 208;
        row = (r < 4) ? r : (112 + r);
    } else {
        int k = j - 1664;
        row = 4 + (k >> 3);
        int c = k & 7;
        col = (c < 4) ? c : (200 + c);
    }
    size_t base = ((size_t)(n * HP_ + row) * WP_ + col) * 16;
    float4 z = make_float4(0.f, 0.f, 0.f, 0.f);
    #pragma unroll
    for (int c4 = 0; c4 < 16; c4++) {
        g_kpad[base + c4] = z;
        g_vpad[base + c4] = z;
    }
}

// ---------------- 1x1 conv + (folded) BN + ReLU -----------------------------
// Tile: 128 pixels x 64 out-channels per 128-thread block.
// Thread (tp = tid&15 -> 8-px group, to = tid>>4 -> 8-out group): 8 out x 8 px,
// accumulated as 8x4 packed f32x2 pairs (pairs along px).
// mode 0: NCHW output.  mode 1: channel-last output with spatial pad.
__global__ __launch_bounds__(128) void conv_kernel(
    const float* __restrict__ in, int layer, float* __restrict__ out,
    int mode, int pad, int Hp, int Wp)
{
    __shared__ float ws[4096];      // weights [ci][o]
    __shared__ float xs[16*128];    // x chunk [ci(16)][px(128)]
    const int tid = threadIdx.x;
    const int tp = tid & 15;
    const int to = tid >> 4;
    const int n  = blockIdx.y;
    const int p0 = blockIdx.x * 128;

    // stage full weight matrix
    {
        const float4* wsrc = (const float4*)(g_Wt + layer*4096);
        float4* wd = (float4*)ws;
        #pragma unroll
        for (int i = 0; i < 8; i++) wd[i*128 + tid] = wsrc[i*128 + tid];
    }

    u64 acc[8][4];
    #pragma unroll
    for (int oi = 0; oi < 8; oi++)
        #pragma unroll
        for (int pj = 0; pj < 4; pj++) acc[oi][pj] = 0ull;

    const unsigned xs_base = (unsigned)__cvta_generic_to_shared(xs) + tp*8*4;
    const float4* ws4 = (const float4*)ws;

    for (int cc = 0; cc < 4; cc++) {
        __syncthreads();
        // stage 16 channels x 128 px (512 float4, 4 per thread)
        #pragma unroll
        for (int i = 0; i < 4; i++) {
            int idx = i*128 + tid;
            int ci  = idx >> 5;     // 0..15
            int p4  = idx & 31;     // 0..31 float4 along px
            ((float4*)xs)[ci*32 + p4] =
                ((const float4*)(in + ((size_t)n*C_ + cc*16 + ci)*HW_ + p0))[p4];
        }
        __syncthreads();
        #pragma unroll
        for (int ci = 0; ci < 16; ci++) {
            u64 x2[4];
            #pragma unroll
            for (int pj = 0; pj < 4; pj++)
                LDS64(x2[pj], xs_base + (ci*128 + pj*2)*4);
            float4 wa = ws4[(cc*16 + ci)*16 + to*2];
            float4 wb = ws4[(cc*16 + ci)*16 + to*2 + 1];
            u64 w2[8];
            PACK2(w2[0], wa.x, wa.x); PACK2(w2[1], wa.y, wa.y);
            PACK2(w2[2], wa.z, wa.z); PACK2(w2[3], wa.w, wa.w);
            PACK2(w2[4], wb.x, wb.x); PACK2(w2[5], wb.y, wb.y);
            PACK2(w2[6], wb.z, wb.z); PACK2(w2[7], wb.w, wb.w);
            #pragma unroll
            for (int oi = 0; oi < 8; oi++)
                #pragma unroll
                for (int pj = 0; pj < 4; pj++)
                    FFMA2(acc[oi][pj], x2[pj], w2[oi]);
        }
    }

    // unpack, bias + relu
    float r[8][8];
    #pragma unroll
    for (int oi = 0; oi < 8; oi++) {
        float bb = g_bf[layer*64 + to*8 + oi];
        #pragma unroll
        for (int pj = 0; pj < 4; pj++) {
            float lo, hi;
            UNPACK2(lo, hi, acc[oi][pj]);
            r[oi][pj*2]   = fmaxf(lo + bb, 0.f);
            r[oi][pj*2+1] = fmaxf(hi + bb, 0.f);
        }
    }

    if (mode == 0) {
        #pragma unroll
        for (int oi = 0; oi < 8; oi++) {
            float* ob = out + ((size_t)n*C_ + to*8 + oi)*HW_ + p0 + tp*8;
            *(float4*)ob       = make_float4(r[oi][0], r[oi][1], r[oi][2], r[oi][3]);
            *(float4*)(ob + 4) = make_float4(r[oi][4], r[oi][5], r[oi][6], r[oi][7]);
        }
    } else {
        #pragma unroll
        for (int p = 0; p < 8; p++) {
            int px = p0 + tp*8 + p;
            int h = px / W_;
            int w = px - h*W_;
            float* ob = out + (((size_t)(n*Hp + h + pad))*Wp + (w + pad))*64 + to*8;
            *(float4*)ob       = make_float4(r[0][p], r[1][p], r[2][p], r[3][p]);
            *(float4*)(ob + 4) = make_float4(r[4][p], r[5][p], r[6][p], r[7][p]);
        }
    }
}

// ---------------- fused similarity + softmax + weighting --------------------
// (unchanged — smem-bound; separate experiment later)
__global__ __launch_bounds__(256, 2) void attn_kernel(float* __restrict__ out)
{
    __shared__ float4 hs[4][16][41];
    const int tid = threadIdx.x;
    const int tx = tid & 31;
    const int ty = tid >> 5;
    const int w0 = blockIdx.x * 32;
    const int h0 = blockIdx.y * 8;
    const int n  = blockIdx.z;
    const int w = w0 + tx;
    const int h = h0 + ty;
    const bool valid = (w < W_);
    const int qpx = (n*H_ + h)*W_ + (valid ? w : 0);

    float acc[NTAP];
    #pragma unroll
    for (int t = 0; t < NTAP; t++) acc[t] = 0.f;

    // ---- phase 1: local similarity ----
    for (int g = 0; g < 4; g++) {
        __syncthreads();
        #pragma unroll
        for (int i = 0; i < 10; i++) {
            int lin = i*256 + tid;
            int c   = lin & 3;
            int col = (lin >> 2) % 40;
            int r   = lin / 160;
            int wp  = w0 + col;
            float4 val = make_float4(0.f, 0.f, 0.f, 0.f);
            if (wp < WP_)
                val = g_kpad[((size_t)(n*HP_ + h0 + r)*WP_ + wp)*16 + g*4 + c];
            hs[c][r][col] = val;
        }
        __syncthreads();
        #pragma unroll
        for (int c4 = 0; c4 < 4; c4++) {
            float4 qv = g_q[(size_t)qpx*16 + g*4 + c4];
            const float4* hb = &hs[c4][ty][tx];
            #pragma unroll
            for (int di = 0; di < 9; di++)
                #pragma unroll
                for (int dj = 0; dj < 9; dj++) {
                    float4 kv = hb[di*41 + dj];
                    acc[di*9 + dj] += qv.x*kv.x + qv.y*kv.y + qv.z*kv.z + qv.w*kv.w;
                }
        }
    }

    // ---- softmax over 81 taps (scale by 1/sqrt(64)) ----
    float mx = acc[0];
    #pragma unroll
    for (int t = 1; t < NTAP; t++) mx = fmaxf(mx, acc[t]);
    float sum = 0.f;
    #pragma unroll
    for (int t = 0; t < NTAP; t++) {
        float e = __expf((acc[t] - mx) * 0.125f);
        acc[t] = e;
        sum += e;
    }
    float inv = 1.f / sum;
    #pragma unroll
    for (int t = 0; t < NTAP; t++) acc[t] *= inv;

    // ---- phase 2: local weighting of V ----
    for (int g = 0; g < 4; g++) {
        __syncthreads();
        #pragma unroll
        for (int i = 0; i < 10; i++) {
            int lin = i*256 + tid;
            int c   = lin & 3;
            int col = (lin >> 2) % 40;
            int r   = lin / 160;
            int wp  = w0 + col;
            float4 val = make_float4(0.f, 0.f, 0.f, 0.f);
            if (wp < WP_)
                val = g_vpad[((size_t)(n*HP_ + h0 + r)*WP_ + wp)*16 + g*4 + c];
            hs[c][r][col] = val;
        }
        __syncthreads();
        #pragma unroll
        for (int c4 = 0; c4 < 4; c4++) {
            float4 ov = make_float4(0.f, 0.f, 0.f, 0.f);
            const float4* hb = &hs[c4][ty][tx];
            #pragma unroll
            for (int di = 0; di < 9; di++)
                #pragma unroll
                for (int dj = 0; dj < 9; dj++) {
                    float4 vv = hb[di*41 + dj];
                    float wt = acc[di*9 + dj];
                    ov.x += wt*vv.x; ov.y += wt*vv.y; ov.z += wt*vv.z; ov.w += wt*vv.w;
                }
            if (valid) {
                int cbase = g*16 + c4*4;
                float* ob = out + ((size_t)(n*C_ + cbase)*H_ + h)*W_ + w;
                ob[0]       = ov.x;
                ob[HW_]     = ov.y;
                ob[2*HW_]   = ov.z;
                ob[3*HW_]   = ov.w;
            }
        }
    }
}

// ---------------- launch ----------------------------------------------------
extern "C" void kernel_launch(void* const* d_in, const int* in_sizes, int n_in,
                              void* d_out, int out_size)
{
    (void)in_sizes; (void)n_in; (void)out_size;
    const float* img  = (const float*)d_in[0];
    const float* wimg = (const float*)d_in[1];
    const float* wc   = (const float*)d_in[2];
    const float* gg   = (const float*)d_in[3];
    const float* bb   = (const float*)d_in[4];
    const float* mm   = (const float*)d_in[5];
    const float* vv   = (const float*)d_in[6];
    float* out = (float*)d_out;

    float *p_tmp, *p_q, *p_kpad, *p_vpad;
    cudaGetSymbolAddress((void**)&p_tmp,  g_tmp);
    cudaGetSymbolAddress((void**)&p_q,    g_q);
    cudaGetSymbolAddress((void**)&p_kpad, g_kpad);
    cudaGetSymbolAddress((void**)&p_vpad, g_vpad);

    prep_kernel<<<80, 256>>>(wc, gg, bb, mm, vv);
    zero_border_kernel<<<(BN_*2560 + 255)/256, 256>>>();

    dim3 cgrid(HW_/128, BN_);   // 175 x 6
    // query = CBR1(CBR0(img))
    conv_kernel<<<cgrid, 128>>>(img,   0, p_tmp, 0, 0, 0, 0);
    conv_kernel<<<cgrid, 128>>>(p_tmp, 1, p_q,   1, 0, H_, W_);
    // key = CBR3(CBR2(wimg))   (padded channel-last)
    conv_kernel<<<cgrid, 128>>>(wimg,  2, p_tmp, 0, 0, 0, 0);
    conv_kernel<<<cgrid, 128>>>(p_tmp, 3, p_kpad, 1, PAD_, HP_, WP_);
    // value = CBR4(wimg)       (padded channel-last)
    conv_kernel<<<cgrid, 128>>>(wimg,  4, p_vpad, 1, PAD_, HP_, WP_);

    dim3 agrid((W_ + 31)/32, H_/8, BN_);   // 7 x 14 x 6
    attn_kernel<<<agrid, 256>>>(out);
}

// round 6
// speedup vs baseline: 1.2827x; 1.2827x over previous
#include <cuda_runtime.h>
#include <math.h>

// Problem constants
#define H_    112
#define W_    200
#define HW_   (H_*W_)        // 22400
#define C_    64
#define BN_   6
#define PAD_  4
#define HP_   (H_ + 2*PAD_)  // 120
#define WP_   (W_ + 2*PAD_)  // 208
#define HPWP_ (HP_*WP_)      // 24960
#define QW_   208            // padded Q width
#define NTAP  81

// tf32 round (b32 destination register, bit-pattern is valid fp32)
__device__ __forceinline__ float tf32r(float x) {
    unsigned u;
    asm("cvt.rna.tf32.f32 %0, %1;" : "=r"(u) : "f"(x));
    return __uint_as_float(u);
}

// ---------------- scratch (static device memory; no allocations) ------------
__device__ float4 g_q   [BN_*H_*QW_*16];  // query, [n][h][w(208)][c] channel-last (tf32 vals)
__device__ float4 g_kpad[BN_*HPWP_*16];   // key,   [n][hp][wp][c] padded channel-last
__device__ float4 g_vpad[BN_*HPWP_*16];   // value, padded channel-last
__device__ float  g_tmp [BN_*C_*HW_];     // intermediate conv activation (NCHW, full fp32)
__device__ float  g_Wt  [5*64*64];        // folded weights, [layer][c_in][c_out]
__device__ float  g_bf  [5*64];           // folded bias

// ---------------- BN folding ------------------------------------------------
__global__ void prep_kernel(const float* __restrict__ wc, const float* __restrict__ g,
                            const float* __restrict__ b,  const float* __restrict__ m,
                            const float* __restrict__ v) {
    int idx = blockIdx.x * 256 + threadIdx.x;
    if (idx < 5*64*64) {
        int l  = idx >> 12;
        int r  = idx & 4095;
        int ci = r >> 6;
        int o  = r & 63;
        float s = g[l*64 + o] * rsqrtf(v[l*64 + o] + 1e-5f);
        g_Wt[idx] = s * wc[(l*64 + o)*64 + ci];   // transposed: [ci][o]
    }
    if (idx < 5*64) {
        float s = g[idx] * rsqrtf(v[idx] + 1e-5f);
        g_bf[idx] = b[idx] - s * m[idx];
    }
}

// ---------------- zero pad borders of K/V and Q column pad ------------------
__global__ void zero_border_kernel() {
    int idx = blockIdx.x * 256 + threadIdx.x;
    const int kvTotal = BN_ * 2560;
    float4 z = make_float4(0.f, 0.f, 0.f, 0.f);
    if (idx < kvTotal) {
        int n = idx / 2560;
        int j = idx - n * 2560;
        int row, col;
        if (j < 1664) {
            int r = j / 208;
            col = j - r * 208;
            row = (r < 4) ? r : (112 + r);
        } else {
            int k = j - 1664;
            row = 4 + (k >> 3);
            int c = k & 7;
            col = (c < 4) ? c : (200 + c);
        }
        size_t base = ((size_t)(n * HP_ + row) * WP_ + col) * 16;
        #pragma unroll
        for (int c4 = 0; c4 < 16; c4++) {
            g_kpad[base + c4] = z;
            g_vpad[base + c4] = z;
        }
    } else if (idx < kvTotal + BN_*H_*8) {
        int qi = idx - kvTotal;
        int n = qi / (H_*8);
        int rr = qi - n*(H_*8);
        int h = rr >> 3;
        int c = rr & 7;
        size_t base = ((size_t)(n*H_ + h)*QW_ + 200 + c) * 16;
        #pragma unroll
        for (int c4 = 0; c4 < 16; c4++) g_q[base + c4] = z;
    }
}

// ---------------- 1x1 conv + (folded) BN + ReLU  (round-1 proven form) ------
// Tile: 64 pixels x 64 out-channels per 128-thread block.
// mode 0: NCHW fp32 output.  mode 1: channel-last padded output, tf32-rounded.
__global__ __launch_bounds__(128) void conv_kernel(
    const float* __restrict__ in, int layer, float* __restrict__ out,
    int mode, int pad, int Hp, int Wp)
{
    __shared__ float ws[4096];     // weights [ci][o]
    __shared__ float xs[16*64];    // x chunk [ci(16)][px(64)]
    const int tid = threadIdx.x;
    const int tp = tid & 15;
    const int to = tid >> 4;
    const int n  = blockIdx.y;
    const int p0 = blockIdx.x * 64;

    const float* wsrc = g_Wt + layer*4096;
    #pragma unroll
    for (int i = 0; i < 32; i++) ws[i*128 + tid] = wsrc[i*128 + tid];

    const float* inb = in + (size_t)n*C_*HW_ + p0;

    float acc[8][4];
    #pragma unroll
    for (int oi = 0; oi < 8; oi++)
        #pragma unroll
        for (int pj = 0; pj < 4; pj++) acc[oi][pj] = 0.f;

    const float4* ws4 = (const float4*)ws;
    const float4* xs4 = (const float4*)xs;

    for (int cc = 0; cc < 4; cc++) {
        __syncthreads();
        #pragma unroll
        for (int r = 0; r < 8; r++) {
            int lin = r*128 + tid;          // lin = ci*64 + px
            int ci  = lin >> 6;
            int px  = lin & 63;
            xs[lin] = inb[(cc*16 + ci)*HW_ + px];
        }
        __syncthreads();
        #pragma unroll
        for (int ci = 0; ci < 16; ci++) {
            float4 xv = xs4[ci*16 + tp];
            float4 wa = ws4[(cc*16 + ci)*16 + to*2];
            float4 wb = ws4[(cc*16 + ci)*16 + to*2 + 1];
            float wv[8] = {wa.x, wa.y, wa.z, wa.w, wb.x, wb.y, wb.z, wb.w};
            float xp[4] = {xv.x, xv.y, xv.z, xv.w};
            #pragma unroll
            for (int oi = 0; oi < 8; oi++)
                #pragma unroll
                for (int pj = 0; pj < 4; pj++)
                    acc[oi][pj] += wv[oi] * xp[pj];
        }
    }

    #pragma unroll
    for (int oi = 0; oi < 8; oi++) {
        float bb = g_bf[layer*64 + to*8 + oi];
        #pragma unroll
        for (int pj = 0; pj < 4; pj++)
            acc[oi][pj] = fmaxf(acc[oi][pj] + bb, 0.f);
    }

    if (mode == 0) {
        float* ob = out + (size_t)n*C_*HW_ + p0 + tp*4;
        #pragma unroll
        for (int oi = 0; oi < 8; oi++) {
            float4 vv = make_float4(acc[oi][0], acc[oi][1], acc[oi][2], acc[oi][3]);
            *(float4*)&ob[(to*8 + oi)*HW_] = vv;
        }
    } else {
        // tf32-round for tensor-core consumers
        #pragma unroll
        for (int oi = 0; oi < 8; oi++)
            #pragma unroll
            for (int pj = 0; pj < 4; pj++)
                acc[oi][pj] = tf32r(acc[oi][pj]);
        #pragma unroll
        for (int pj = 0; pj < 4; pj++) {
            int px = p0 + tp*4 + pj;
            int h = px / W_;
            int w = px - h*W_;
            float* ob = out + (((size_t)(n*Hp + h + pad))*Wp + (w + pad))*64 + to*8;
            *(float4*)ob       = make_float4(acc[0][pj], acc[1][pj], acc[2][pj], acc[3][pj]);
            *(float4*)(ob + 4) = make_float4(acc[4][pj], acc[5][pj], acc[6][pj], acc[7][pj]);
        }
    }
}

// ---------------- tensor-core attention -------------------------------------
// Block: 256 thr = 8 warps; warp wid handles query row h0+wid, w-tile of 16.
// KV smem tile: [16 rows][24 cols][64ch + 4 pad] fp32.
// Phase 1: per di, S[16px x 24cols] via 3n x 8k mma.m16n8k8.tf32; band -> sacc.
// Softmax in-warp.  Phase 2: out[64ch x 16px] via 4m x 2n x 3k mma per di,
// B built on the fly from the weight band.

#define TR_   16
#define TC_   24
#define CPAD_ 68
#define KV_F  (TR_*TC_*CPAD_)       // 26112 f32
#define SACC_F (8*16*84)            // 10752
#define SFUL_F (8*16*24)            // 3072
#define SMEM_F (KV_F + SACC_F + SFUL_F + 8*16)
#define SMEM_BYTES (SMEM_F*4)

__device__ __forceinline__ void mma_tf32(float c[4], const float a[4], float b0, float b1) {
    const unsigned* A = (const unsigned*)a;
    asm("mma.sync.aligned.m16n8k8.row.col.f32.tf32.tf32.f32 "
        "{%0,%1,%2,%3}, {%4,%5,%6,%7}, {%8,%9}, {%0,%1,%2,%3};"
        : "+f"(c[0]), "+f"(c[1]), "+f"(c[2]), "+f"(c[3])
        : "r"(A[0]), "r"(A[1]), "r"(A[2]), "r"(A[3]),
          "r"(__float_as_uint(b0)), "r"(__float_as_uint(b1)));
}

__global__ __launch_bounds__(256, 1) void attn_kernel(float* __restrict__ out)
{
    extern __shared__ float smem[];
    float* kv   = smem;                       // [16][24][68]
    float* sacc = smem + KV_F;                // [8][16][84]
    float* sful = sacc + SACC_F;              // [8][16][24]
    float* sinv = sful + SFUL_F;              // [8][16]

    const int tid  = threadIdx.x;
    const int wid  = tid >> 5;
    const int lane = tid & 31;
    const int g    = lane >> 2;
    const int tg   = lane & 3;
    const int n  = blockIdx.z;
    const int h0 = blockIdx.y * 8;
    const int w0 = blockIdx.x * 16;
    const int h  = h0 + wid;                  // query row (always < 112)

    // ---- stage K tile ----
    {
        const float4* kb = g_kpad + (size_t)(n*HP_ + h0) * WP_ * 16;
        for (int i = tid; i < TR_*TC_*16; i += 256) {
            int px = i >> 4, c4 = i & 15;
            int r = px / TC_, c = px - r*TC_;
            int pcol = w0 + c; if (pcol > 207) pcol = 207;
            float4 v = kb[((size_t)r*WP_ + pcol)*16 + c4];
            *(float4*)(kv + px*CPAD_ + c4*4) = v;
        }
    }

    // ---- load Q A-fragments (held for all phase-1 mmas) ----
    float qa[8][4];
    {
        const float* qb = (const float*)g_q + ((size_t)(n*H_ + h)*QW_) * 64;
        #pragma unroll
        for (int k = 0; k < 8; k++) {
            qa[k][0] = qb[(w0 + g)    *64 + k*8 + tg];
            qa[k][1] = qb[(w0 + g + 8)*64 + k*8 + tg];
            qa[k][2] = qb[(w0 + g)    *64 + k*8 + tg + 4];
            qa[k][3] = qb[(w0 + g + 8)*64 + k*8 + tg + 4];
        }
    }
    __syncthreads();

    // ---- phase 1: similarity per di ----
    float* sf = sful + wid*(16*24);
    float* sa = sacc + wid*(16*84);
    #pragma unroll 1
    for (int di = 0; di < 9; di++) {
        float c0[3][4];
        #pragma unroll
        for (int nt = 0; nt < 3; nt++)
            #pragma unroll
            for (int j = 0; j < 4; j++) c0[nt][j] = 0.f;
        const float* krow = kv + (wid + di)*(TC_*CPAD_);
        #pragma unroll
        for (int nt = 0; nt < 3; nt++) {
            const float* kc = krow + (nt*8 + g)*CPAD_;
            #pragma unroll
            for (int k = 0; k < 8; k++) {
                float b0 = kc[k*8 + tg];
                float b1 = kc[k*8 + tg + 4];
                mma_tf32(c0[nt], qa[k], b0, b1);
            }
        }
        // write S tile [16][24]
        #pragma unroll
        for (int nt = 0; nt < 3; nt++) {
            sf[g*24     + nt*8 + 2*tg]     = c0[nt][0];
            sf[g*24     + nt*8 + 2*tg + 1] = c0[nt][1];
            sf[(g+8)*24 + nt*8 + 2*tg]     = c0[nt][2];
            sf[(g+8)*24 + nt*8 + 2*tg + 1] = c0[nt][3];
        }
        __syncwarp();
        // band copy: 144 elems -> sacc[px][di*9+dj]
        #pragma unroll
        for (int e = lane; e < 144; e += 32) {
            int px = e / 9, dj = e - px*9;
            sa[px*84 + di*9 + dj] = sf[px*24 + px + dj];
        }
        __syncwarp();
    }

    // ---- softmax (2 lanes per px: taps [0,41) / [41,81)) ----
    {
        int px   = lane & 15;
        int half = lane >> 4;
        float* sp = sa + px*84;
        int t0 = half * 41;
        int tc = 41 - half;          // 41 or 40
        float mx = -1e30f;
        for (int t = 0; t < tc; t++) {
            float v = sp[t0 + t] * 0.125f;
            mx = fmaxf(mx, v);
        }
        mx = fmaxf(mx, __shfl_xor_sync(0xffffffffu, mx, 16));
        float sum = 0.f;
        for (int t = 0; t < tc; t++) {
            float e = __expf(sp[t0 + t] * 0.125f - mx);
            sum += e;
            sp[t0 + t] = tf32r(e);
        }
        sum += __shfl_xor_sync(0xffffffffu, sum, 16);
        if (half == 0) sinv[wid*16 + px] = 1.f / sum;
    }
    __syncthreads();   // all warps done with K tile before overwrite

    // ---- stage V tile (reuse kv) ----
    {
        const float4* vb = g_vpad + (size_t)(n*HP_ + h0) * WP_ * 16;
        for (int i = tid; i < TR_*TC_*16; i += 256) {
            int px = i >> 4, c4 = i & 15;
            int r = px / TC_, c = px - r*TC_;
            int pcol = w0 + c; if (pcol > 207) pcol = 207;
            float4 v = vb[((size_t)r*WP_ + pcol)*16 + c4];
            *(float4*)(kv + px*CPAD_ + c4*4) = v;
        }
    }
    __syncthreads();

    // ---- phase 2: weighting ----
    float oc[4][2][4];
    #pragma unroll
    for (int mt = 0; mt < 4; mt++)
        #pragma unroll
        for (int nt = 0; nt < 2; nt++)
            #pragma unroll
            for (int j = 0; j < 4; j++) oc[mt][nt][j] = 0.f;

    #pragma unroll 1
    for (int di = 0; di < 9; di++) {
        const float* vrow = kv + (wid + di)*(TC_*CPAD_);
        #pragma unroll
        for (int kst = 0; kst < 3; kst++) {
            // B fragments (2 n-tiles), built from weight band
            float bb[2][2];
            #pragma unroll
            for (int nt = 0; nt < 2; nt++) {
                int i0 = nt*8 + g;           // n-col = px
                int j0 = kst*8 + tg;         // k-row = w'
                int dj0 = j0 - i0;
                int dj1 = dj0 + 4;
                bb[nt][0] = ((unsigned)dj0 <= 8u) ? sa[i0*84 + di*9 + dj0] : 0.f;
                bb[nt][1] = ((unsigned)dj1 <= 8u) ? sa[i0*84 + di*9 + dj1] : 0.f;
            }
            #pragma unroll
            for (int mt = 0; mt < 4; mt++) {
                float av[4];
                av[0] = vrow[(kst*8 + tg)    *CPAD_ + mt*16 + g];
                av[1] = vrow[(kst*8 + tg)    *CPAD_ + mt*16 + g + 8];
                av[2] = vrow[(kst*8 + tg + 4)*CPAD_ + mt*16 + g];
                av[3] = vrow[(kst*8 + tg + 4)*CPAD_ + mt*16 + g + 8];
                mma_tf32(oc[mt][0], av, bb[0][0], bb[0][1]);
                mma_tf32(oc[mt][1], av, bb[1][0], bb[1][1]);
            }
        }
    }

    // ---- epilogue: scale by 1/sum, store NCHW ----
    #pragma unroll
    for (int nt = 0; nt < 2; nt++) {
        int pxl = nt*8 + 2*tg;
        float is0 = sinv[wid*16 + pxl];
        float is1 = sinv[wid*16 + pxl + 1];
        int w = w0 + pxl;
        #pragma unroll
        for (int mt = 0; mt < 4; mt++) {
            int c  = mt*16 + g;
            float* ob0 = out + ((size_t)(n*C_ + c)*H_ + h)*W_;
            float* ob1 = out + ((size_t)(n*C_ + c + 8)*H_ + h)*W_;
            if (w < W_) {
                ob0[w] = oc[mt][nt][0] * is0;
                ob1[w] = oc[mt][nt][2] * is0;
            }
            if (w + 1 < W_) {
                ob0[w+1] = oc[mt][nt][1] * is1;
                ob1[w+1] = oc[mt][nt][3] * is1;
            }
        }
    }
}

// ---------------- launch ----------------------------------------------------
extern "C" void kernel_launch(void* const* d_in, const int* in_sizes, int n_in,
                              void* d_out, int out_size)
{
    (void)in_sizes; (void)n_in; (void)out_size;
    const float* img  = (const float*)d_in[0];
    const float* wimg = (const float*)d_in[1];
    const float* wc   = (const float*)d_in[2];
    const float* gg   = (const float*)d_in[3];
    const float* bb   = (const float*)d_in[4];
    const float* mm   = (const float*)d_in[5];
    const float* vv   = (const float*)d_in[6];
    float* out = (float*)d_out;

    float *p_tmp, *p_q, *p_kpad, *p_vpad;
    cudaGetSymbolAddress((void**)&p_tmp,  g_tmp);
    cudaGetSymbolAddress((void**)&p_q,    g_q);
    cudaGetSymbolAddress((void**)&p_kpad, g_kpad);
    cudaGetSymbolAddress((void**)&p_vpad, g_vpad);

    static int smem_set = 0;
    if (!smem_set) {
        cudaFuncSetAttribute(attn_kernel,
                             cudaFuncAttributeMaxDynamicSharedMemorySize, SMEM_BYTES);
        smem_set = 1;
    }

    prep_kernel<<<80, 256>>>(wc, gg, bb, mm, vv);
    zero_border_kernel<<<(BN_*2560 + BN_*H_*8 + 255)/256, 256>>>();

    dim3 cgrid(HW_/64, BN_);   // 350 x 6
    // query = CBR1(CBR0(img))  -> channel-last width-208, tf32
    conv_kernel<<<cgrid, 128>>>(img,   0, p_tmp, 0, 0, 0, 0);
    conv_kernel<<<cgrid, 128>>>(p_tmp, 1, p_q,   1, 0, H_, QW_);
    // key = CBR3(CBR2(wimg))   -> padded channel-last, tf32
    conv_kernel<<<cgrid, 128>>>(wimg,  2, p_tmp, 0, 0, 0, 0);
    conv_kernel<<<cgrid, 128>>>(p_tmp, 3, p_kpad, 1, PAD_, HP_, WP_);
    // value = CBR4(wimg)       -> padded channel-last, tf32
    conv_kernel<<<cgrid, 128>>>(wimg,  4, p_vpad, 1, PAD_, HP_, WP_);

    dim3 agrid((W_ + 15)/16, H_/8, BN_);   // 13 x 14 x 6
    attn_kernel<<<agrid, 256, SMEM_BYTES>>>(out);
}

// round 7
// speedup vs baseline: 1.9476x; 1.5183x over previous
#include <cuda_runtime.h>
#include <math.h>

// Problem constants
#define H_    112
#define W_    200
#define HW_   (H_*W_)        // 22400
#define C_    64
#define BN_   6
#define PAD_  4
#define HP_   (H_ + 2*PAD_)  // 120
#define WP_   (W_ + 2*PAD_)  // 208
#define HPWP_ (HP_*WP_)      // 24960
#define QW_   208
#define NTAP  81

// tf32 round (rna), b32 destination
__device__ __forceinline__ float tf32r(float x) {
    unsigned u;
    asm("cvt.rna.tf32.f32 %0, %1;" : "=r"(u) : "f"(x));
    return __uint_as_float(u);
}

__device__ __forceinline__ void mma_tf32(float c[4], const float a[4], float b0, float b1) {
    const unsigned* A = (const unsigned*)a;
    asm("mma.sync.aligned.m16n8k8.row.col.f32.tf32.tf32.f32 "
        "{%0,%1,%2,%3}, {%4,%5,%6,%7}, {%8,%9}, {%0,%1,%2,%3};"
        : "+f"(c[0]), "+f"(c[1]), "+f"(c[2]), "+f"(c[3])
        : "r"(A[0]), "r"(A[1]), "r"(A[2]), "r"(A[3]),
          "r"(__float_as_uint(b0)), "r"(__float_as_uint(b1)));
}

// ---------------- scratch -----------------------------------------------------
__device__ float4 g_q   [BN_*H_*QW_*16];  // [n][h][w208][c] channel-last tf32
__device__ float4 g_kpad[BN_*HPWP_*16];   // [n][hp][wp][c] padded channel-last
__device__ float4 g_vpad[BN_*HPWP_*16];
__device__ float4 g_Wf4 [5*8*4*32];       // weight A-fragments: [l][k0][m0][lane]{4}
__device__ float  g_bf  [5*64];           // folded bias

// ---------------- prep: BN fold + weight fragment packing --------------------
__global__ void prep_kernel(const float* __restrict__ wc, const float* __restrict__ gam,
                            const float* __restrict__ bet, const float* __restrict__ mu,
                            const float* __restrict__ var) {
    int idx = blockIdx.x * 256 + threadIdx.x;
    if (idx < 5*8*4*32*4) {
        int l  = idx >> 12;
        int r  = idx & 4095;
        int k0 = r >> 9;
        int r2 = r & 511;
        int m0 = r2 >> 7;
        int r3 = r2 & 127;
        int lane = r3 >> 2;
        int j    = r3 & 3;
        int g  = lane >> 2;
        int tg = lane & 3;
        int o  = m0*16 + g + ((j & 1) ? 8 : 0);
        int ci = k0*8 + tg + ((j >= 2) ? 4 : 0);
        float s = gam[l*64 + o] * rsqrtf(var[l*64 + o] + 1e-5f);
        ((float*)g_Wf4)[idx] = tf32r(s * wc[(l*64 + o)*64 + ci]);
    }
    if (idx < 5*64) {
        float s = gam[idx] * rsqrtf(var[idx] + 1e-5f);
        g_bf[idx] = bet[idx] - s * mu[idx];
    }
}

// ---------------- zero pad borders of K/V and Q column pad -------------------
__global__ void zero_border_kernel() {
    int idx = blockIdx.x * 256 + threadIdx.x;
    const int kvTotal = BN_ * 2560;
    float4 z = make_float4(0.f, 0.f, 0.f, 0.f);
    if (idx < kvTotal) {
        int n = idx / 2560;
        int j = idx - n * 2560;
        int row, col;
        if (j < 1664) {
            int r = j / 208;
            col = j - r * 208;
            row = (r < 4) ? r : (112 + r);
        } else {
            int k = j - 1664;
            row = 4 + (k >> 3);
            int c = k & 7;
            col = (c < 4) ? c : (200 + c);
        }
        size_t base = ((size_t)(n * HP_ + row) * WP_ + col) * 16;
        #pragma unroll
        for (int c4 = 0; c4 < 16; c4++) {
            g_kpad[base + c4] = z;
            g_vpad[base + c4] = z;
        }
    } else if (idx < kvTotal + BN_*H_*8) {
        int qi = idx - kvTotal;
        int n = qi / (H_*8);
        int rr = qi - n*(H_*8);
        int h = rr >> 3;
        int c = rr & 7;
        size_t base = ((size_t)(n*H_ + h)*QW_ + 200 + c) * 16;
        #pragma unroll
        for (int c4 = 0; c4 < 16; c4++) g_q[base + c4] = z;
    }
}

// ---------------- fused 5-layer QKV via tensor cores -------------------------
// Block: 128 thr = 4 warps. Each warp: 32 px, all 64 channels, layers chained
// via two per-warp smem buffers [64ci][40]. A = weight frags (gmem, L1-hot),
// B = activations (smem, conflict-free: bank = (8tg+g)%32 distinct).

#define XSTRIDE 40
#define BUF_F   (64*XSTRIDE)     // 2560 floats per buffer
#define QKV_SMEM (4*2*BUF_F*4)   // 81920 bytes

__device__ __forceinline__ void stage_tile(const float* __restrict__ src, float* buf, int lane) {
    int ci0 = lane >> 3;        // 0..3
    int px4 = lane & 7;         // 0..7
    #pragma unroll
    for (int it = 0; it < 16; it++) {
        int ci = it*4 + ci0;
        float4 v = *(const float4*)(src + (size_t)ci*HW_ + px4*4);
        v.x = tf32r(v.x); v.y = tf32r(v.y); v.z = tf32r(v.z); v.w = tf32r(v.w);
        *(float4*)(buf + ci*XSTRIDE + px4*4) = v;
    }
}

__device__ __forceinline__ void layer_mma(const float* buf, int l, int lane, float c[4][4][4]) {
    int g = lane >> 2, tg = lane & 3;
    #pragma unroll
    for (int m = 0; m < 4; m++)
        #pragma unroll
        for (int nt = 0; nt < 4; nt++)
            #pragma unroll
            for (int j = 0; j < 4; j++) c[m][nt][j] = 0.f;

    const float4* wf = g_Wf4 + (size_t)l*8*4*32;
    #pragma unroll
    for (int k0 = 0; k0 < 8; k0++) {
        float4 a[4];
        #pragma unroll
        for (int m = 0; m < 4; m++)
            a[m] = __ldg(wf + (k0*4 + m)*32 + lane);
        #pragma unroll
        for (int nt = 0; nt < 4; nt++) {
            float b0 = buf[(k0*8 + tg)    *XSTRIDE + nt*8 + g];
            float b1 = buf[(k0*8 + tg + 4)*XSTRIDE + nt*8 + g];
            #pragma unroll
            for (int m = 0; m < 4; m++)
                mma_tf32(c[m][nt], (const float*)&a[m], b0, b1);
        }
    }
}

// bias + relu + tf32 round -> smem buffer [o][40] for next layer
__device__ __forceinline__ void epi_smem(float c[4][4][4], float* bufo, int l, int lane) {
    int g = lane >> 2, tg = lane & 3;
    #pragma unroll
    for (int m = 0; m < 4; m++) {
        float b0 = g_bf[l*64 + m*16 + g];
        float b1 = g_bf[l*64 + m*16 + g + 8];
        #pragma unroll
        for (int nt = 0; nt < 4; nt++) {
            int px = nt*8 + 2*tg;
            bufo[(m*16 + g)    *XSTRIDE + px]     = tf32r(fmaxf(c[m][nt][0] + b0, 0.f));
            bufo[(m*16 + g)    *XSTRIDE + px + 1] = tf32r(fmaxf(c[m][nt][1] + b0, 0.f));
            bufo[(m*16 + g + 8)*XSTRIDE + px]     = tf32r(fmaxf(c[m][nt][2] + b1, 0.f));
            bufo[(m*16 + g + 8)*XSTRIDE + px + 1] = tf32r(fmaxf(c[m][nt][3] + b1, 0.f));
        }
    }
}

// bias + relu + tf32 round -> channel-last gmem (base pre-offset for padding)
__device__ __forceinline__ void epi_gmem(float c[4][4][4], float* base, int l, int lane, int px0) {
    int g = lane >> 2, tg = lane & 3;
    float bs0[4], bs1[4];
    #pragma unroll
    for (int m = 0; m < 4; m++) {
        bs0[m] = g_bf[l*64 + m*16 + g];
        bs1[m] = g_bf[l*64 + m*16 + g + 8];
    }
    #pragma unroll
    for (int nt = 0; nt < 4; nt++) {
        #pragma unroll
        for (int j = 0; j < 2; j++) {
            int px = px0 + nt*8 + 2*tg + j;
            int h = px / W_;
            int w = px - h*W_;
            float* p = base + ((size_t)h*WP_ + w)*64;
            #pragma unroll
            for (int m = 0; m < 4; m++) {
                p[m*16 + g]     = tf32r(fmaxf(c[m][nt][j]     + bs0[m], 0.f));
                p[m*16 + g + 8] = tf32r(fmaxf(c[m][nt][2 + j] + bs1[m], 0.f));
            }
        }
    }
}

__global__ __launch_bounds__(128) void qkv_kernel(const float* __restrict__ img,
                                                  const float* __restrict__ wimg)
{
    extern __shared__ float xs[];
    const int tid = threadIdx.x;
    const int wid = tid >> 5;
    const int lane = tid & 31;
    const int n = blockIdx.y;
    const int px0 = (blockIdx.x*4 + wid) * 32;

    float* bufA = xs + wid * (2*BUF_F);
    float* bufB = bufA + BUF_F;
    float c[4][4][4];

    const float* wsrc = wimg + (size_t)n*C_*HW_ + px0;
    const float* isrc = img  + (size_t)n*C_*HW_ + px0;
    float* qb = (float*)g_q    + (size_t)n*H_*QW_*64;                     // no pad
    float* kb = (float*)g_kpad + (((size_t)n*HP_ + PAD_)*WP_ + PAD_)*64;
    float* vb = (float*)g_vpad + (((size_t)n*HP_ + PAD_)*WP_ + PAD_)*64;

    // warped source -> v (L4), -> k (L2,L3)
    stage_tile(wsrc, bufA, lane);  __syncwarp();
    layer_mma(bufA, 4, lane, c);   epi_gmem(c, vb, 4, lane, px0);
    layer_mma(bufA, 2, lane, c);   epi_smem(c, bufB, 2, lane);  __syncwarp();
    layer_mma(bufB, 3, lane, c);   epi_gmem(c, kb, 3, lane, px0);
    // target source -> q (L0,L1)
    stage_tile(isrc, bufA, lane);  __syncwarp();
    layer_mma(bufA, 0, lane, c);   epi_smem(c, bufB, 0, lane);  __syncwarp();
    layer_mma(bufB, 1, lane, c);   epi_gmem(c, qb, 1, lane, px0);
}

// ---------------- tensor-core attention (unchanged, proven round-6) ----------
#define TR_   16
#define TC_   24
#define CPAD_ 68
#define KV_F  (TR_*TC_*CPAD_)
#define SACC_F (8*16*84)
#define SFUL_F (8*16*24)
#define SMEM_F (KV_F + SACC_F + SFUL_F + 8*16)
#define SMEM_BYTES (SMEM_F*4)

__global__ __launch_bounds__(256, 1) void attn_kernel(float* __restrict__ out)
{
    extern __shared__ float smem[];
    float* kv   = smem;
    float* sacc = smem + KV_F;
    float* sful = sacc + SACC_F;
    float* sinv = sful + SFUL_F;

    const int tid  = threadIdx.x;
    const int wid  = tid >> 5;
    const int lane = tid & 31;
    const int g    = lane >> 2;
    const int tg   = lane & 3;
    const int n  = blockIdx.z;
    const int h0 = blockIdx.y * 8;
    const int w0 = blockIdx.x * 16;
    const int h  = h0 + wid;

    {
        const float4* kb = g_kpad + (size_t)(n*HP_ + h0) * WP_ * 16;
        for (int i = tid; i < TR_*TC_*16; i += 256) {
            int px = i >> 4, c4 = i & 15;
            int r = px / TC_, c = px - r*TC_;
            int pcol = w0 + c; if (pcol > 207) pcol = 207;
            float4 v = kb[((size_t)r*WP_ + pcol)*16 + c4];
            *(float4*)(kv + px*CPAD_ + c4*4) = v;
        }
    }

    float qa[8][4];
    {
        const float* qb = (const float*)g_q + ((size_t)(n*H_ + h)*QW_) * 64;
        #pragma unroll
        for (int k = 0; k < 8; k++) {
            qa[k][0] = qb[(w0 + g)    *64 + k*8 + tg];
            qa[k][1] = qb[(w0 + g + 8)*64 + k*8 + tg];
            qa[k][2] = qb[(w0 + g)    *64 + k*8 + tg + 4];
            qa[k][3] = qb[(w0 + g + 8)*64 + k*8 + tg + 4];
        }
    }
    __syncthreads();

    float* sf = sful + wid*(16*24);
    float* sa = sacc + wid*(16*84);
    #pragma unroll 1
    for (int di = 0; di < 9; di++) {
        float c0[3][4];
        #pragma unroll
        for (int nt = 0; nt < 3; nt++)
            #pragma unroll
            for (int j = 0; j < 4; j++) c0[nt][j] = 0.f;
        const float* krow = kv + (wid + di)*(TC_*CPAD_);
        #pragma unroll
        for (int nt = 0; nt < 3; nt++) {
            const float* kc = krow + (nt*8 + g)*CPAD_;
            #pragma unroll
            for (int k = 0; k < 8; k++) {
                float b0 = kc[k*8 + tg];
                float b1 = kc[k*8 + tg + 4];
                mma_tf32(c0[nt], qa[k], b0, b1);
            }
        }
        #pragma unroll
        for (int nt = 0; nt < 3; nt++) {
            sf[g*24     + nt*8 + 2*tg]     = c0[nt][0];
            sf[g*24     + nt*8 + 2*tg + 1] = c0[nt][1];
            sf[(g+8)*24 + nt*8 + 2*tg]     = c0[nt][2];
            sf[(g+8)*24 + nt*8 + 2*tg + 1] = c0[nt][3];
        }
        __syncwarp();
        #pragma unroll
        for (int e = lane; e < 144; e += 32) {
            int px = e / 9, dj = e - px*9;
            sa[px*84 + di*9 + dj] = sf[px*24 + px + dj];
        }
        __syncwarp();
    }

    {
        int px   = lane & 15;
        int half = lane >> 4;
        float* sp = sa + px*84;
        int t0 = half * 41;
        int tc = 41 - half;
        float mx = -1e30f;
        for (int t = 0; t < tc; t++) {
            float v = sp[t0 + t] * 0.125f;
            mx = fmaxf(mx, v);
        }
        mx = fmaxf(mx, __shfl_xor_sync(0xffffffffu, mx, 16));
        float sum = 0.f;
        for (int t = 0; t < tc; t++) {
            float e = __expf(sp[t0 + t] * 0.125f - mx);
            sum += e;
            sp[t0 + t] = tf32r(e);
        }
        sum += __shfl_xor_sync(0xffffffffu, sum, 16);
        if (half == 0) sinv[wid*16 + px] = 1.f / sum;
    }
    __syncthreads();

    {
        const float4* vb = g_vpad + (size_t)(n*HP_ + h0) * WP_ * 16;
        for (int i = tid; i < TR_*TC_*16; i += 256) {
            int px = i >> 4, c4 = i & 15;
            int r = px / TC_, c = px - r*TC_;
            int pcol = w0 + c; if (pcol > 207) pcol = 207;
            float4 v = vb[((size_t)r*WP_ + pcol)*16 + c4];
            *(float4*)(kv + px*CPAD_ + c4*4) = v;
        }
    }
    __syncthreads();

    float oc[4][2][4];
    #pragma unroll
    for (int mt = 0; mt < 4; mt++)
        #pragma unroll
        for (int nt = 0; nt < 2; nt++)
            #pragma unroll
            for (int j = 0; j < 4; j++) oc[mt][nt][j] = 0.f;

    #pragma unroll 1
    for (int di = 0; di < 9; di++) {
        const float* vrow = kv + (wid + di)*(TC_*CPAD_);
        #pragma unroll
        for (int kst = 0; kst < 3; kst++) {
            float bb[2][2];
            #pragma unroll
            for (int nt = 0; nt < 2; nt++) {
                int i0 = nt*8 + g;
                int j0 = kst*8 + tg;
                int dj0 = j0 - i0;
                int dj1 = dj0 + 4;
                bb[nt][0] = ((unsigned)dj0 <= 8u) ? sa[i0*84 + di*9 + dj0] : 0.f;
                bb[nt][1] = ((unsigned)dj1 <= 8u) ? sa[i0*84 + di*9 + dj1] : 0.f;
            }
            #pragma unroll
            for (int mt = 0; mt < 4; mt++) {
                float av[4];
                av[0] = vrow[(kst*8 + tg)    *CPAD_ + mt*16 + g];
                av[1] = vrow[(kst*8 + tg)    *CPAD_ + mt*16 + g + 8];
                av[2] = vrow[(kst*8 + tg + 4)*CPAD_ + mt*16 + g];
                av[3] = vrow[(kst*8 + tg + 4)*CPAD_ + mt*16 + g + 8];
                mma_tf32(oc[mt][0], av, bb[0][0], bb[0][1]);
                mma_tf32(oc[mt][1], av, bb[1][0], bb[1][1]);
            }
        }
    }

    #pragma unroll
    for (int nt = 0; nt < 2; nt++) {
        int pxl = nt*8 + 2*tg;
        float is0 = sinv[wid*16 + pxl];
        float is1 = sinv[wid*16 + pxl + 1];
        int w = w0 + pxl;
        #pragma unroll
        for (int mt = 0; mt < 4; mt++) {
            int c  = mt*16 + g;
            float* ob0 = out + ((size_t)(n*C_ + c)*H_ + h)*W_;
            float* ob1 = out + ((size_t)(n*C_ + c + 8)*H_ + h)*W_;
            if (w < W_) {
                ob0[w] = oc[mt][nt][0] * is0;
                ob1[w] = oc[mt][nt][2] * is0;
            }
            if (w + 1 < W_) {
                ob0[w+1] = oc[mt][nt][1] * is1;
                ob1[w+1] = oc[mt][nt][3] * is1;
            }
        }
    }
}

// ---------------- launch ------------------------------------------------------
extern "C" void kernel_launch(void* const* d_in, const int* in_sizes, int n_in,
                              void* d_out, int out_size)
{
    (void)in_sizes; (void)n_in; (void)out_size;
    const float* img  = (const float*)d_in[0];
    const float* wimg = (const float*)d_in[1];
    const float* wc   = (const float*)d_in[2];
    const float* gg   = (const float*)d_in[3];
    const float* bb   = (const float*)d_in[4];
    const float* mm   = (const float*)d_in[5];
    const float* vv   = (const float*)d_in[6];
    float* out = (float*)d_out;

    static int attr_set = 0;
    if (!attr_set) {
        cudaFuncSetAttribute(attn_kernel,
                             cudaFuncAttributeMaxDynamicSharedMemorySize, SMEM_BYTES);
        cudaFuncSetAttribute(qkv_kernel,
                             cudaFuncAttributeMaxDynamicSharedMemorySize, QKV_SMEM);
        attr_set = 1;
    }

    prep_kernel<<<81, 256>>>(wc, gg, bb, mm, vv);
    zero_border_kernel<<<(BN_*2560 + BN_*H_*8 + 255)/256, 256>>>();

    dim3 qgrid(HW_/128, BN_);   // 175 x 6
    qkv_kernel<<<qgrid, 128, QKV_SMEM>>>(img, wimg);

    dim3 agrid((W_ + 15)/16, H_/8, BN_);   // 13 x 14 x 6
    attn_kernel<<<agrid, 256, SMEM_BYTES>>>(out);
}

// round 8
// speedup vs baseline: 2.0196x; 1.0370x over previous
#include <cuda_runtime.h>
#include <math.h>

// Problem constants
#define H_    112
#define W_    200
#define HW_   (H_*W_)        // 22400
#define C_    64
#define BN_   6
#define PAD_  4
#define HP_   (H_ + 2*PAD_)  // 120
#define WP_   (W_ + 2*PAD_)  // 208
#define HPWP_ (HP_*WP_)      // 24960
#define QW_   208
#define NTAP  81

// tf32 round (rna), b32 destination
__device__ __forceinline__ float tf32r(float x) {
    unsigned u;
    asm("cvt.rna.tf32.f32 %0, %1;" : "=r"(u) : "f"(x));
    return __uint_as_float(u);
}

__device__ __forceinline__ void mma_tf32(float c[4], const float a[4], float b0, float b1) {
    const unsigned* A = (const unsigned*)a;
    asm("mma.sync.aligned.m16n8k8.row.col.f32.tf32.tf32.f32 "
        "{%0,%1,%2,%3}, {%4,%5,%6,%7}, {%8,%9}, {%0,%1,%2,%3};"
        : "+f"(c[0]), "+f"(c[1]), "+f"(c[2]), "+f"(c[3])
        : "r"(A[0]), "r"(A[1]), "r"(A[2]), "r"(A[3]),
          "r"(__float_as_uint(b0)), "r"(__float_as_uint(b1)));
}

// ---------------- scratch -----------------------------------------------------
__device__ float4 g_q   [BN_*H_*QW_*16];  // [n][h][w208][c] channel-last tf32
__device__ float4 g_kpad[BN_*HPWP_*16];   // [n][hp][wp][c] padded channel-last
__device__ float4 g_vpad[BN_*HPWP_*16];
__device__ float4 g_Wf4 [5*8*4*32];       // weight A-fragments: [l][k0][m0][lane]{4}
__device__ float  g_bf  [5*64];           // folded bias

// ---------------- prep: BN fold + weight fragment packing --------------------
__global__ void prep_kernel(const float* __restrict__ wc, const float* __restrict__ gam,
                            const float* __restrict__ bet, const float* __restrict__ mu,
                            const float* __restrict__ var) {
    int idx = blockIdx.x * 256 + threadIdx.x;
    if (idx < 5*8*4*32*4) {
        int l  = idx >> 12;
        int r  = idx & 4095;
        int k0 = r >> 9;
        int r2 = r & 511;
        int m0 = r2 >> 7;
        int r3 = r2 & 127;
        int lane = r3 >> 2;
        int j    = r3 & 3;
        int g  = lane >> 2;
        int tg = lane & 3;
        int o  = m0*16 + g + ((j & 1) ? 8 : 0);
        int ci = k0*8 + tg + ((j >= 2) ? 4 : 0);
        float s = gam[l*64 + o] * rsqrtf(var[l*64 + o] + 1e-5f);
        ((float*)g_Wf4)[idx] = tf32r(s * wc[(l*64 + o)*64 + ci]);
    }
    if (idx < 5*64) {
        float s = gam[idx] * rsqrtf(var[idx] + 1e-5f);
        g_bf[idx] = bet[idx] - s * mu[idx];
    }
}

// ---------------- zero pad borders of K/V and Q column pad -------------------
__global__ void zero_border_kernel() {
    int idx = blockIdx.x * 256 + threadIdx.x;
    const int kvTotal = BN_ * 2560;
    float4 z = make_float4(0.f, 0.f, 0.f, 0.f);
    if (idx < kvTotal) {
        int n = idx / 2560;
        int j = idx - n * 2560;
        int row, col;
        if (j < 1664) {
            int r = j / 208;
            col = j - r * 208;
            row = (r < 4) ? r : (112 + r);
        } else {
            int k = j - 1664;
            row = 4 + (k >> 3);
            int c = k & 7;
            col = (c < 4) ? c : (200 + c);
        }
        size_t base = ((size_t)(n * HP_ + row) * WP_ + col) * 16;
        #pragma unroll
        for (int c4 = 0; c4 < 16; c4++) {
            g_kpad[base + c4] = z;
            g_vpad[base + c4] = z;
        }
    } else if (idx < kvTotal + BN_*H_*8) {
        int qi = idx - kvTotal;
        int n = qi / (H_*8);
        int rr = qi - n*(H_*8);
        int h = rr >> 3;
        int c = rr & 7;
        size_t base = ((size_t)(n*H_ + h)*QW_ + 200 + c) * 16;
        #pragma unroll
        for (int c4 = 0; c4 < 16; c4++) g_q[base + c4] = z;
    }
}

// ---------------- fused 5-layer QKV via tensor cores (proven round-7) --------
#define XSTRIDE 40
#define BUF_F   (64*XSTRIDE)
#define QKV_SMEM (4*2*BUF_F*4)

__device__ __forceinline__ void stage_tile(const float* __restrict__ src, float* buf, int lane) {
    int ci0 = lane >> 3;
    int px4 = lane & 7;
    #pragma unroll
    for (int it = 0; it < 16; it++) {
        int ci = it*4 + ci0;
        float4 v = *(const float4*)(src + (size_t)ci*HW_ + px4*4);
        v.x = tf32r(v.x); v.y = tf32r(v.y); v.z = tf32r(v.z); v.w = tf32r(v.w);
        *(float4*)(buf + ci*XSTRIDE + px4*4) = v;
    }
}

__device__ __forceinline__ void layer_mma(const float* buf, int l, int lane, float c[4][4][4]) {
    int g = lane >> 2, tg = lane & 3;
    #pragma unroll
    for (int m = 0; m < 4; m++)
        #pragma unroll
        for (int nt = 0; nt < 4; nt++)
            #pragma unroll
            for (int j = 0; j < 4; j++) c[m][nt][j] = 0.f;

    const float4* wf = g_Wf4 + (size_t)l*8*4*32;
    #pragma unroll
    for (int k0 = 0; k0 < 8; k0++) {
        float4 a[4];
        #pragma unroll
        for (int m = 0; m < 4; m++)
            a[m] = __ldg(wf + (k0*4 + m)*32 + lane);
        #pragma unroll
        for (int nt = 0; nt < 4; nt++) {
            float b0 = buf[(k0*8 + tg)    *XSTRIDE + nt*8 + g];
            float b1 = buf[(k0*8 + tg + 4)*XSTRIDE + nt*8 + g];
            #pragma unroll
            for (int m = 0; m < 4; m++)
                mma_tf32(c[m][nt], (const float*)&a[m], b0, b1);
        }
    }
}

__device__ __forceinline__ void epi_smem(float c[4][4][4], float* bufo, int l, int lane) {
    int g = lane >> 2, tg = lane & 3;
    #pragma unroll
    for (int m = 0; m < 4; m++) {
        float b0 = g_bf[l*64 + m*16 + g];
        float b1 = g_bf[l*64 + m*16 + g + 8];
        #pragma unroll
        for (int nt = 0; nt < 4; nt++) {
            int px = nt*8 + 2*tg;
            bufo[(m*16 + g)    *XSTRIDE + px]     = tf32r(fmaxf(c[m][nt][0] + b0, 0.f));
            bufo[(m*16 + g)    *XSTRIDE + px + 1] = tf32r(fmaxf(c[m][nt][1] + b0, 0.f));
            bufo[(m*16 + g + 8)*XSTRIDE + px]     = tf32r(fmaxf(c[m][nt][2] + b1, 0.f));
            bufo[(m*16 + g + 8)*XSTRIDE + px + 1] = tf32r(fmaxf(c[m][nt][3] + b1, 0.f));
        }
    }
}

__device__ __forceinline__ void epi_gmem(float c[4][4][4], float* base, int l, int lane, int px0) {
    int g = lane >> 2, tg = lane & 3;
    float bs0[4], bs1[4];
    #pragma unroll
    for (int m = 0; m < 4; m++) {
        bs0[m] = g_bf[l*64 + m*16 + g];
        bs1[m] = g_bf[l*64 + m*16 + g + 8];
    }
    #pragma unroll
    for (int nt = 0; nt < 4; nt++) {
        #pragma unroll
        for (int j = 0; j < 2; j++) {
            int px = px0 + nt*8 + 2*tg + j;
            int h = px / W_;
            int w = px - h*W_;
            float* p = base + ((size_t)h*WP_ + w)*64;
            #pragma unroll
            for (int m = 0; m < 4; m++) {
                p[m*16 + g]     = tf32r(fmaxf(c[m][nt][j]     + bs0[m], 0.f));
                p[m*16 + g + 8] = tf32r(fmaxf(c[m][nt][2 + j] + bs1[m], 0.f));
            }
        }
    }
}

__global__ __launch_bounds__(128) void qkv_kernel(const float* __restrict__ img,
                                                  const float* __restrict__ wimg)
{
    extern __shared__ float xs[];
    const int tid = threadIdx.x;
    const int wid = tid >> 5;
    const int lane = tid & 31;
    const int n = blockIdx.y;
    const int px0 = (blockIdx.x*4 + wid) * 32;

    float* bufA = xs + wid * (2*BUF_F);
    float* bufB = bufA + BUF_F;
    float c[4][4][4];

    const float* wsrc = wimg + (size_t)n*C_*HW_ + px0;
    const float* isrc = img  + (size_t)n*C_*HW_ + px0;
    float* qb = (float*)g_q    + (size_t)n*H_*QW_*64;
    float* kb = (float*)g_kpad + (((size_t)n*HP_ + PAD_)*WP_ + PAD_)*64;
    float* vb = (float*)g_vpad + (((size_t)n*HP_ + PAD_)*WP_ + PAD_)*64;

    stage_tile(wsrc, bufA, lane);  __syncwarp();
    layer_mma(bufA, 4, lane, c);   epi_gmem(c, vb, 4, lane, px0);
    layer_mma(bufA, 2, lane, c);   epi_smem(c, bufB, 2, lane);  __syncwarp();
    layer_mma(bufB, 3, lane, c);   epi_gmem(c, kb, 3, lane, px0);
    stage_tile(isrc, bufA, lane);  __syncwarp();
    layer_mma(bufA, 0, lane, c);   epi_smem(c, bufB, 0, lane);  __syncwarp();
    layer_mma(bufB, 1, lane, c);   epi_gmem(c, qb, 1, lane, px0);
}

// ---------------- tensor-core attention, channel-split for 2 CTAs/SM ---------
#define TR_   16
#define TC_   24
#define CPAD2 36                        // 32 ch + 4 pad (B-loads conflict-free)
#define KV2_F  (TR_*TC_*CPAD2)          // 13824 f
#define SACC_F (8*16*84)                // 10752
#define SFUL_F (8*16*24)                // 3072
#define SMEM2_F (KV2_F + SACC_F + SFUL_F + 8*16)
#define SMEM2_BYTES (SMEM2_F*4)         // 111104 B -> 2 CTAs/SM

__global__ __launch_bounds__(256, 2) void attn_kernel(float* __restrict__ out)
{
    extern __shared__ float smem[];
    float* kv   = smem;                 // [16][24][36]
    float* sacc = smem + KV2_F;         // [8][16][84]
    float* sful = sacc + SACC_F;        // [8][16][24]
    float* sinv = sful + SFUL_F;        // [8][16]

    const int tid  = threadIdx.x;
    const int wid  = tid >> 5;
    const int lane = tid & 31;
    const int g    = lane >> 2;
    const int tg   = lane & 3;
    const int n  = blockIdx.z;
    const int h0 = blockIdx.y * 8;
    const int w0 = blockIdx.x * 16;
    const int h  = h0 + wid;

    // ---- Q fragments for all 64 channels ----
    float qa[8][4];
    {
        const float* qb = (const float*)g_q + ((size_t)(n*H_ + h)*QW_) * 64;
        #pragma unroll
        for (int k = 0; k < 8; k++) {
            qa[k][0] = qb[(w0 + g)    *64 + k*8 + tg];
            qa[k][1] = qb[(w0 + g + 8)*64 + k*8 + tg];
            qa[k][2] = qb[(w0 + g)    *64 + k*8 + tg + 4];
            qa[k][3] = qb[(w0 + g + 8)*64 + k*8 + tg + 4];
        }
    }

    float* sf = sful + wid*(16*24);
    float* sa = sacc + wid*(16*84);

    // ---- phase 1: similarity, two 32-channel passes ----
    #pragma unroll 1
    for (int cp = 0; cp < 2; cp++) {
        __syncthreads();
        {
            const float4* kb = g_kpad + (size_t)(n*HP_ + h0) * WP_ * 16;
            for (int i = tid; i < TR_*TC_*8; i += 256) {
                int px = i >> 3, c4 = i & 7;
                int r = px / TC_, c = px - r*TC_;
                int pcol = w0 + c; if (pcol > 207) pcol = 207;
                float4 v = kb[((size_t)r*WP_ + pcol)*16 + cp*8 + c4];
                *(float4*)(kv + px*CPAD2 + c4*4) = v;
            }
        }
        __syncthreads();
        #pragma unroll 1
        for (int di = 0; di < 9; di++) {
            float c0[3][4];
            #pragma unroll
            for (int nt = 0; nt < 3; nt++)
                #pragma unroll
                for (int j = 0; j < 4; j++) c0[nt][j] = 0.f;
            const float* krow = kv + (wid + di)*(TC_*CPAD2);
            #pragma unroll
            for (int nt = 0; nt < 3; nt++) {
                const float* kc = krow + (nt*8 + g)*CPAD2;
                #pragma unroll
                for (int k = 0; k < 4; k++) {
                    float b0 = kc[k*8 + tg];
                    float b1 = kc[k*8 + tg + 4];
                    mma_tf32(c0[nt], qa[cp*4 + k], b0, b1);
                }
            }
            #pragma unroll
            for (int nt = 0; nt < 3; nt++) {
                sf[g*24     + nt*8 + 2*tg]     = c0[nt][0];
                sf[g*24     + nt*8 + 2*tg + 1] = c0[nt][1];
                sf[(g+8)*24 + nt*8 + 2*tg]     = c0[nt][2];
                sf[(g+8)*24 + nt*8 + 2*tg + 1] = c0[nt][3];
            }
            __syncwarp();
            if (cp == 0) {
                #pragma unroll
                for (int e = lane; e < 144; e += 32) {
                    int px = e / 9, dj = e - px*9;
                    sa[px*84 + di*9 + dj] = sf[px*24 + px + dj];
                }
            } else {
                #pragma unroll
                for (int e = lane; e < 144; e += 32) {
                    int px = e / 9, dj = e - px*9;
                    sa[px*84 + di*9 + dj] += sf[px*24 + px + dj];
                }
            }
            __syncwarp();
        }
    }

    // ---- softmax (2 lanes per px) ----
    {
        int px   = lane & 15;
        int half = lane >> 4;
        float* sp = sa + px*84;
        int t0 = half * 41;
        int tc = 41 - half;
        float mx = -1e30f;
        for (int t = 0; t < tc; t++) {
            float v = sp[t0 + t] * 0.125f;
            mx = fmaxf(mx, v);
        }
        mx = fmaxf(mx, __shfl_xor_sync(0xffffffffu, mx, 16));
        float sum = 0.f;
        for (int t = 0; t < tc; t++) {
            float e = __expf(sp[t0 + t] * 0.125f - mx);
            sum += e;
            sp[t0 + t] = tf32r(e);
        }
        sum += __shfl_xor_sync(0xffffffffu, sum, 16);
        if (half == 0) sinv[wid*16 + px] = 1.f / sum;
    }

    // ---- phase 2: weighting, two 32-channel passes ----
    #pragma unroll 1
    for (int vp = 0; vp < 2; vp++) {
        __syncthreads();
        {
            const float4* vb = g_vpad + (size_t)(n*HP_ + h0) * WP_ * 16;
            for (int i = tid; i < TR_*TC_*8; i += 256) {
                int px = i >> 3, c4 = i & 7;
                int r = px / TC_, c = px - r*TC_;
                int pcol = w0 + c; if (pcol > 207) pcol = 207;
                float4 v = vb[((size_t)r*WP_ + pcol)*16 + vp*8 + c4];
                *(float4*)(kv + px*CPAD2 + c4*4) = v;
            }
        }
        __syncthreads();

        float oc[2][2][4];
        #pragma unroll
        for (int mt = 0; mt < 2; mt++)
            #pragma unroll
            for (int nt = 0; nt < 2; nt++)
                #pragma unroll
                for (int j = 0; j < 4; j++) oc[mt][nt][j] = 0.f;

        #pragma unroll 1
        for (int di = 0; di < 9; di++) {
            const float* vrow = kv + (wid + di)*(TC_*CPAD2);
            #pragma unroll
            for (int kst = 0; kst < 3; kst++) {
                float bb[2][2];
                #pragma unroll
                for (int nt = 0; nt < 2; nt++) {
                    int i0 = nt*8 + g;
                    int j0 = kst*8 + tg;
                    int dj0 = j0 - i0;
                    int dj1 = dj0 + 4;
                    bb[nt][0] = ((unsigned)dj0 <= 8u) ? sa[i0*84 + di*9 + dj0] : 0.f;
                    bb[nt][1] = ((unsigned)dj1 <= 8u) ? sa[i0*84 + di*9 + dj1] : 0.f;
                }
                #pragma unroll
                for (int mt = 0; mt < 2; mt++) {
                    float av[4];
                    av[0] = vrow[(kst*8 + tg)    *CPAD2 + mt*16 + g];
                    av[1] = vrow[(kst*8 + tg)    *CPAD2 + mt*16 + g + 8];
                    av[2] = vrow[(kst*8 + tg + 4)*CPAD2 + mt*16 + g];
                    av[3] = vrow[(kst*8 + tg + 4)*CPAD2 + mt*16 + g + 8];
                    mma_tf32(oc[mt][0], av, bb[0][0], bb[0][1]);
                    mma_tf32(oc[mt][1], av, bb[1][0], bb[1][1]);
                }
            }
        }

        // store this pass's 32 channels
        #pragma unroll
        for (int nt = 0; nt < 2; nt++) {
            int pxl = nt*8 + 2*tg;
            float is0 = sinv[wid*16 + pxl];
            float is1 = sinv[wid*16 + pxl + 1];
            int w = w0 + pxl;
            #pragma unroll
            for (int mt = 0; mt < 2; mt++) {
                int c  = vp*32 + mt*16 + g;
                float* ob0 = out + ((size_t)(n*C_ + c)*H_ + h)*W_;
                float* ob1 = out + ((size_t)(n*C_ + c + 8)*H_ + h)*W_;
                if (w < W_) {
                    ob0[w] = oc[mt][nt][0] * is0;
                    ob1[w] = oc[mt][nt][2] * is0;
                }
                if (w + 1 < W_) {
                    ob0[w+1] = oc[mt][nt][1] * is1;
                    ob1[w+1] = oc[mt][nt][3] * is1;
                }
            }
        }
    }
}

// ---------------- launch ------------------------------------------------------
extern "C" void kernel_launch(void* const* d_in, const int* in_sizes, int n_in,
                              void* d_out, int out_size)
{
    (void)in_sizes; (void)n_in; (void)out_size;
    const float* img  = (const float*)d_in[0];
    const float* wimg = (const float*)d_in[1];
    const float* wc   = (const float*)d_in[2];
    const float* gg   = (const float*)d_in[3];
    const float* bb   = (const float*)d_in[4];
    const float* mm   = (const float*)d_in[5];
    const float* vv   = (const float*)d_in[6];
    float* out = (float*)d_out;

    static int attr_set = 0;
    if (!attr_set) {
        cudaFuncSetAttribute(attn_kernel,
                             cudaFuncAttributeMaxDynamicSharedMemorySize, SMEM2_BYTES);
        cudaFuncSetAttribute(qkv_kernel,
                             cudaFuncAttributeMaxDynamicSharedMemorySize, QKV_SMEM);
        attr_set = 1;
    }

    prep_kernel<<<81, 256>>>(wc, gg, bb, mm, vv);
    zero_border_kernel<<<(BN_*2560 + BN_*H_*8 + 255)/256, 256>>>();

    dim3 qgrid(HW_/128, BN_);   // 175 x 6
    qkv_kernel<<<qgrid, 128, QKV_SMEM>>>(img, wimg);

    dim3 agrid((W_ + 15)/16, H_/8, BN_);   // 13 x 14 x 6
    attn_kernel<<<agrid, 256, SMEM2_BYTES>>>(out);
}